// round 4
// baseline (speedup 1.0000x reference)
#include <cuda_runtime.h>
#include <cuda_bf16.h>
#include <math.h>
#include <stdint.h>

#define S_LEN   2048
#define DMODEL  1024
#define NHEADS  16
#define DK      64
#define BATCH   2
#define MROWS   (BATCH * S_LEN)   // 4096

typedef unsigned short ushort_t;

// ---------------------------------------------------------------------------
// Device scratch
// ---------------------------------------------------------------------------
// bf16 hi/lo activations (GEMM inputs)
__device__ __align__(16) ushort_t g_Xhi[(size_t)MROWS * DMODEL];
__device__ __align__(16) ushort_t g_Xlo[(size_t)MROWS * DMODEL];
__device__ __align__(16) ushort_t g_Yhi[(size_t)MROWS * DMODEL];
__device__ __align__(16) ushort_t g_Ylo[(size_t)MROWS * DMODEL];
__device__ __align__(16) ushort_t g_Zhi[(size_t)MROWS * DMODEL];
__device__ __align__(16) ushort_t g_Zlo[(size_t)MROWS * DMODEL];
// bf16 hi/lo projected Q/K/V (GEMM outputs, flash inputs)
__device__ __align__(16) ushort_t g_Qhi[(size_t)MROWS * DMODEL];
__device__ __align__(16) ushort_t g_Qlo[(size_t)MROWS * DMODEL];
__device__ __align__(16) ushort_t g_Khi[(size_t)MROWS * DMODEL];
__device__ __align__(16) ushort_t g_Klo[(size_t)MROWS * DMODEL];
__device__ __align__(16) ushort_t g_Vhi[(size_t)MROWS * DMODEL];
__device__ __align__(16) ushort_t g_Vlo[(size_t)MROWS * DMODEL];
// bf16 hi/lo attention output (flash output, out-GEMM input)
__device__ __align__(16) ushort_t g_Ohi[(size_t)MROWS * DMODEL];
__device__ __align__(16) ushort_t g_Olo[(size_t)MROWS * DMODEL];
// bf16 hi/lo transposed weights
__device__ __align__(16) ushort_t g_WqThi[(size_t)DMODEL * DMODEL];
__device__ __align__(16) ushort_t g_WqTlo[(size_t)DMODEL * DMODEL];
__device__ __align__(16) ushort_t g_WkThi[(size_t)DMODEL * DMODEL];
__device__ __align__(16) ushort_t g_WkTlo[(size_t)DMODEL * DMODEL];
__device__ __align__(16) ushort_t g_WvThi[(size_t)DMODEL * DMODEL];
__device__ __align__(16) ushort_t g_WvTlo[(size_t)DMODEL * DMODEL];
__device__ __align__(16) ushort_t g_WoThi[(size_t)DMODEL * DMODEL];
__device__ __align__(16) ushort_t g_WoTlo[(size_t)DMODEL * DMODEL];

// ---------------------------------------------------------------------------
// Low-level helpers
// ---------------------------------------------------------------------------
__device__ __forceinline__ uint32_t smem_u32(const void* p) {
    uint32_t a;
    asm("{ .reg .u64 t; cvta.to.shared.u64 t, %1; cvt.u32.u64 %0, t; }" : "=r"(a) : "l"(p));
    return a;
}
__device__ __forceinline__ void mma_bf16(float* c, const uint32_t* a, const uint32_t* b) {
    asm volatile(
        "mma.sync.aligned.m16n8k16.row.col.f32.bf16.bf16.f32 "
        "{%0,%1,%2,%3}, {%4,%5,%6,%7}, {%8,%9}, {%0,%1,%2,%3};"
        : "+f"(c[0]), "+f"(c[1]), "+f"(c[2]), "+f"(c[3])
        : "r"(a[0]), "r"(a[1]), "r"(a[2]), "r"(a[3]), "r"(b[0]), "r"(b[1]));
}
__device__ __forceinline__ void ldsm_x4(uint32_t* r, uint32_t addr) {
    asm volatile("ldmatrix.sync.aligned.m8n8.x4.shared.b16 {%0,%1,%2,%3}, [%4];"
        : "=r"(r[0]), "=r"(r[1]), "=r"(r[2]), "=r"(r[3]) : "r"(addr));
}
__device__ __forceinline__ void ldsm_x4_t(uint32_t* r, uint32_t addr) {
    asm volatile("ldmatrix.sync.aligned.m8n8.x4.trans.shared.b16 {%0,%1,%2,%3}, [%4];"
        : "=r"(r[0]), "=r"(r[1]), "=r"(r[2]), "=r"(r[3]) : "r"(addr));
}
__device__ __forceinline__ void cp16(uint32_t dst, const void* src) {
    asm volatile("cp.async.cg.shared.global [%0], [%1], 16;" :: "r"(dst), "l"(src));
}
__device__ __forceinline__ void cp_commit() {
    asm volatile("cp.async.commit_group;" ::: "memory");
}
template <int N> __device__ __forceinline__ void cp_wait() {
    asm volatile("cp.async.wait_group %0;" :: "n"(N) : "memory");
}
__device__ __forceinline__ void split1(float x, ushort_t& h, ushort_t& l) {
    __nv_bfloat16 hb = __float2bfloat16(x);
    float rem = x - __bfloat162float(hb);
    __nv_bfloat16 lb = __float2bfloat16(rem);
    h = __bfloat16_as_ushort(hb);
    l = __bfloat16_as_ushort(lb);
}

// ---------------------------------------------------------------------------
// Prep kernels
// ---------------------------------------------------------------------------
__global__ void __launch_bounds__(256) split3_kernel(const float* __restrict__ x0,
                                                     const float* __restrict__ x1,
                                                     const float* __restrict__ x2,
                                                     int n4) {
    const float* x;
    ushort_t *hi, *lo;
    switch (blockIdx.y) {
        case 0:  x = x0; hi = g_Xhi; lo = g_Xlo; break;
        case 1:  x = x1; hi = g_Yhi; lo = g_Ylo; break;
        default: x = x2; hi = g_Zhi; lo = g_Zlo; break;
    }
    int i = blockIdx.x * 256 + threadIdx.x;
    if (i >= n4) return;
    float4 v = ((const float4*)x)[i];
    ushort4 h, l;
    split1(v.x, h.x, l.x);
    split1(v.y, h.y, l.y);
    split1(v.z, h.z, l.z);
    split1(v.w, h.w, l.w);
    ((ushort4*)hi)[i] = h;
    ((ushort4*)lo)[i] = l;
}

__global__ void __launch_bounds__(256) wsplit_kernel(const float* __restrict__ w0,
                                                     const float* __restrict__ w1,
                                                     const float* __restrict__ w2,
                                                     const float* __restrict__ w3) {
    __shared__ float t[32][33];
    const float* W;
    ushort_t *TH, *TL;
    switch (blockIdx.z) {
        case 0: W = w0; TH = g_WqThi; TL = g_WqTlo; break;
        case 1: W = w1; TH = g_WkThi; TL = g_WkTlo; break;
        case 2: W = w2; TH = g_WvThi; TL = g_WvTlo; break;
        default: W = w3; TH = g_WoThi; TL = g_WoTlo; break;
    }
    int tx = threadIdx.x & 31, ty = threadIdx.x >> 5;
    int n0 = blockIdx.x * 32, k0 = blockIdx.y * 32;
#pragma unroll
    for (int j = 0; j < 4; j++)
        t[ty + 8 * j][tx] = W[(size_t)(k0 + ty + 8 * j) * DMODEL + n0 + tx];
    __syncthreads();
#pragma unroll
    for (int j = 0; j < 4; j++) {
        float v = t[tx][ty + 8 * j];
        ushort_t h, l;
        split1(v, h, l);
        size_t o = (size_t)(n0 + ty + 8 * j) * DMODEL + k0 + tx;
        TH[o] = h;
        TL[o] = l;
    }
}

// ---------------------------------------------------------------------------
// HMMA GEMM (bf16x3), 128x128x32 tiles, cp.async double buffer.
// SPLIT_OUT: write bf16 hi/lo (for QKV); else fp32 + nothing else (out proj).
// ---------------------------------------------------------------------------
#define GT_STRIDE 40
#define GT_MAT    (128 * GT_STRIDE * 2)
#define GT_BUF    (4 * GT_MAT)
#define GEMM_SMEM (2 * GT_BUF)

template <bool SPLIT_OUT>
__device__ __forceinline__ void gemm_mma_body(const ushort_t* __restrict__ ahi,
                                              const ushort_t* __restrict__ alo,
                                              const ushort_t* __restrict__ bhi,
                                              const ushort_t* __restrict__ blo,
                                              const float* __restrict__ bias,
                                              float* __restrict__ Cf,
                                              ushort_t* __restrict__ Chi,
                                              ushort_t* __restrict__ Clo) {
    extern __shared__ char smem[];
    const uint32_t sb = smem_u32(smem);
    const int tid = threadIdx.x;
    const int lane = tid & 31;
    const int wid = tid >> 5;
    const int wm = wid >> 1;
    const int wn = wid & 1;
    const int m0 = blockIdx.y * 128;
    const int n0 = blockIdx.x * 128;

    const ushort_t* srcs[4] = { ahi + (size_t)m0 * DMODEL, alo + (size_t)m0 * DMODEL,
                                bhi + (size_t)n0 * DMODEL, blo + (size_t)n0 * DMODEL };

    auto load_chunk = [&](int c, int buf) {
        uint32_t dbase = sb + buf * GT_BUF;
#pragma unroll
        for (int mt = 0; mt < 4; mt++) {
#pragma unroll
            for (int i = 0; i < 2; i++) {
                int idx = tid + i * 256;
                int row = idx >> 2, seg = idx & 3;
                const ushort_t* src = srcs[mt] + (size_t)row * DMODEL + c * 32 + seg * 8;
                cp16(dbase + mt * GT_MAT + (row * GT_STRIDE + seg * 8) * 2, src);
            }
        }
    };

    float acc[2][8][4];
#pragma unroll
    for (int mi = 0; mi < 2; mi++)
#pragma unroll
        for (int j = 0; j < 8; j++)
#pragma unroll
            for (int q = 0; q < 4; q++) acc[mi][j][q] = 0.0f;

    load_chunk(0, 0);
    cp_commit();

    for (int c = 0; c < 32; c++) {
        if (c + 1 < 32) { load_chunk(c + 1, (c + 1) & 1); cp_commit(); }
        if (c + 1 < 32) cp_wait<1>(); else cp_wait<0>();
        __syncthreads();

        const uint32_t base = sb + (c & 1) * GT_BUF;
        const uint32_t A_h = base, A_l = base + GT_MAT;
        const uint32_t B_h = base + 2 * GT_MAT, B_l = base + 3 * GT_MAT;
#pragma unroll
        for (int ks = 0; ks < 2; ks++) {
            uint32_t ah[2][4], al[2][4];
#pragma unroll
            for (int mi = 0; mi < 2; mi++) {
                int row = wm * 32 + mi * 16 + (lane & 15);
                int col = ks * 16 + (lane >> 4) * 8;
                uint32_t off = (row * GT_STRIDE + col) * 2;
                ldsm_x4(ah[mi], A_h + off);
                ldsm_x4(al[mi], A_l + off);
            }
            uint32_t bh[8][2], bl[8][2];
#pragma unroll
            for (int j2 = 0; j2 < 4; j2++) {
                int nr = wn * 64 + j2 * 16 + (lane & 7) + ((lane & 16) ? 8 : 0);
                int kc = ks * 16 + ((lane & 8) ? 8 : 0);
                uint32_t off = (nr * GT_STRIDE + kc) * 2;
                uint32_t t[4];
                ldsm_x4(t, B_h + off);
                bh[2 * j2][0] = t[0]; bh[2 * j2][1] = t[1];
                bh[2 * j2 + 1][0] = t[2]; bh[2 * j2 + 1][1] = t[3];
                ldsm_x4(t, B_l + off);
                bl[2 * j2][0] = t[0]; bl[2 * j2][1] = t[1];
                bl[2 * j2 + 1][0] = t[2]; bl[2 * j2 + 1][1] = t[3];
            }
#pragma unroll
            for (int mi = 0; mi < 2; mi++)
#pragma unroll
                for (int j = 0; j < 8; j++) {
                    mma_bf16(acc[mi][j], ah[mi], bh[j]);
                    mma_bf16(acc[mi][j], ah[mi], bl[j]);
                    mma_bf16(acc[mi][j], al[mi], bh[j]);
                }
        }
        __syncthreads();
    }

#pragma unroll
    for (int mi = 0; mi < 2; mi++) {
#pragma unroll
        for (int j = 0; j < 8; j++) {
            int row = m0 + wm * 32 + mi * 16 + (lane >> 2);
            int col = n0 + wn * 64 + j * 8 + (lane & 3) * 2;
            float2 bb = *(const float2*)&bias[col];
            float v00 = acc[mi][j][0] + bb.x, v01 = acc[mi][j][1] + bb.y;
            float v10 = acc[mi][j][2] + bb.x, v11 = acc[mi][j][3] + bb.y;
            if (SPLIT_OUT) {
                ushort2 h0, l0, h1, l1;
                split1(v00, h0.x, l0.x); split1(v01, h0.y, l0.y);
                split1(v10, h1.x, l1.x); split1(v11, h1.y, l1.y);
                *(ushort2*)&Chi[(size_t)row * DMODEL + col] = h0;
                *(ushort2*)&Clo[(size_t)row * DMODEL + col] = l0;
                *(ushort2*)&Chi[(size_t)(row + 8) * DMODEL + col] = h1;
                *(ushort2*)&Clo[(size_t)(row + 8) * DMODEL + col] = l1;
            } else {
                float2 w0 = { v00, v01 }, w1 = { v10, v11 };
                *(float2*)&Cf[(size_t)row * DMODEL + col] = w0;
                *(float2*)&Cf[(size_t)(row + 8) * DMODEL + col] = w1;
            }
        }
    }
}

__global__ void __launch_bounds__(256) gemm_qkv_tc(const float* __restrict__ bq,
                                                   const float* __restrict__ bk,
                                                   const float* __restrict__ bv) {
    if (blockIdx.z == 0)
        gemm_mma_body<true>(g_Xhi, g_Xlo, g_WqThi, g_WqTlo, bq, nullptr, g_Qhi, g_Qlo);
    else if (blockIdx.z == 1)
        gemm_mma_body<true>(g_Yhi, g_Ylo, g_WkThi, g_WkTlo, bk, nullptr, g_Khi, g_Klo);
    else
        gemm_mma_body<true>(g_Zhi, g_Zlo, g_WvThi, g_WvTlo, bv, nullptr, g_Vhi, g_Vlo);
}

__global__ void __launch_bounds__(256) gemm_out_tc(const float* __restrict__ bo,
                                                   float* __restrict__ C) {
    gemm_mma_body<false>(g_Ohi, g_Olo, g_WoThi, g_WoTlo, bo, C, nullptr, nullptr);
}

// ---------------------------------------------------------------------------
// HMMA flash attention: 128 q-rows x 64 k per iter, 256 threads / 8 warps.
// Pre-split bf16 inputs via cp.async; K/V double-buffered; O written hi/lo.
// ---------------------------------------------------------------------------
#define FL_STRIDE 72
#define FL_QT  (128 * FL_STRIDE * 2)     // 18432 B (one Q matrix)
#define FL_KVT (64 * FL_STRIDE * 2)      // 9216 B  (one K or V matrix)
#define FL_KVBUF (4 * FL_KVT)            // KH,KL,VH,VL
#define FL_QH  0
#define FL_QL  (FL_QH + FL_QT)
#define FL_KV  (FL_QL + FL_QT)           // 2 buffers
#define FL_PH  (FL_KV + 2 * FL_KVBUF)
#define FL_PL  (FL_PH + FL_QT)
#define FL_PAD (FL_PL + FL_QT)
#define FL_SMEM (FL_PAD + 256)           // 147712 B

__global__ void __launch_bounds__(256) flash_mma(const float* __restrict__ pad_mask,
                                                 const float* __restrict__ look_mask) {
    extern __shared__ char smc[];
    const uint32_t sb = smem_u32(smc);
    const uint32_t uQH = sb + FL_QH, uQL = sb + FL_QL;
    const uint32_t uPH = sb + FL_PH, uPL = sb + FL_PL;
    float* pads = (float*)(smc + FL_PAD);

    const int tid = threadIdx.x;
    const int lane = tid & 31;
    const int warp = tid >> 5;
    const int qt = blockIdx.x, h = blockIdx.y, b = blockIdx.z;
    const int q0 = qt * 128;

    const size_t hoff = (size_t)h * DK;

    // Q tile load (128x64 hi+lo): 2048 cp16
    {
        const ushort_t* QH = g_Qhi + (size_t)(b * S_LEN + q0) * DMODEL + hoff;
        const ushort_t* QL = g_Qlo + (size_t)(b * S_LEN + q0) * DMODEL + hoff;
#pragma unroll
        for (int i = 0; i < 8; i++) {
            int idx = tid + i * 256;
            int mat = idx >> 10, rem = idx & 1023;
            int row = rem >> 3, seg = rem & 7;
            const ushort_t* src = (mat ? QL : QH) + (size_t)row * DMODEL + seg * 8;
            cp16((mat ? uQL : uQH) + (row * FL_STRIDE + seg * 8) * 2, src);
        }
    }

    auto load_kv = [&](int kt, int buf) {
        const int k0 = kt * 64;
        const size_t base = (size_t)(b * S_LEN + k0) * DMODEL + hoff;
        const ushort_t* srcs[4] = { g_Khi + base, g_Klo + base, g_Vhi + base, g_Vlo + base };
        const uint32_t dbase = sb + FL_KV + buf * FL_KVBUF;
#pragma unroll
        for (int i = 0; i < 8; i++) {
            int idx = tid + i * 256;
            int sel = idx >> 9, rem = idx & 511;
            int row = rem >> 3, seg = rem & 7;
            cp16(dbase + sel * FL_KVT + (row * FL_STRIDE + seg * 8) * 2,
                 srcs[sel] + (size_t)row * DMODEL + seg * 8);
        }
    };

    const int nkt = 2 * qt + 2;   // 64-wide k-tiles covering causal span
    load_kv(0, 0);
    cp_commit();

    float o[8][4];
    float mrow[2] = { -INFINITY, -INFINITY };
    float lrow[2] = { 0.0f, 0.0f };
#pragma unroll
    for (int j = 0; j < 8; j++)
#pragma unroll
        for (int q = 0; q < 4; q++) o[j][q] = 0.0f;

    const int rl0 = warp * 16 + (lane >> 2);
    const int rl1 = rl0 + 8;

    for (int kt = 0; kt < nkt; kt++) {
        const int buf = kt & 1;
        const int k0 = kt * 64;
        if (kt + 1 < nkt) { load_kv(kt + 1, buf ^ 1); cp_commit(); }
        if (tid < 64) pads[tid] = pad_mask[b * S_LEN + k0 + tid];
        if (kt + 1 < nkt) cp_wait<1>(); else cp_wait<0>();
        __syncthreads();

        const uint32_t kvb = sb + FL_KV + buf * FL_KVBUF;
        const uint32_t uKH = kvb, uKL = kvb + FL_KVT;
        const uint32_t uVH = kvb + 2 * FL_KVT, uVL = kvb + 3 * FL_KVT;

        // which q-rows need masking: tile diag if k0 range overlaps row range
        const bool diag = (k0 + 63 >= q0 + warp * 16) && (k0 <= q0 + warp * 16 + 15);
        const bool full_mask_tile = (k0 > q0 + warp * 16 + 15);  // never (nkt bound), safe

        // ---- S = Q @ K^T ----
        float sc[8][4];
#pragma unroll
        for (int j = 0; j < 8; j++)
#pragma unroll
            for (int q = 0; q < 4; q++) sc[j][q] = 0.0f;

#pragma unroll
        for (int ks = 0; ks < 4; ks++) {
            uint32_t ah[4], al[4];
            {
                int row = warp * 16 + (lane & 15);
                int col = ks * 16 + (lane >> 4) * 8;
                uint32_t off = (row * FL_STRIDE + col) * 2;
                ldsm_x4(ah, uQH + off);
                ldsm_x4(al, uQL + off);
            }
#pragma unroll
            for (int j2 = 0; j2 < 4; j2++) {
                int nr = j2 * 16 + (lane & 7) + ((lane & 16) ? 8 : 0);
                int kc = ks * 16 + ((lane & 8) ? 8 : 0);
                uint32_t off = (nr * FL_STRIDE + kc) * 2;
                uint32_t th[4], tl[4];
                ldsm_x4(th, uKH + off);
                ldsm_x4(tl, uKL + off);
                mma_bf16(sc[2 * j2],     ah, &th[0]);
                mma_bf16(sc[2 * j2],     ah, &tl[0]);
                mma_bf16(sc[2 * j2],     al, &th[0]);
                mma_bf16(sc[2 * j2 + 1], ah, &th[2]);
                mma_bf16(sc[2 * j2 + 1], ah, &tl[2]);
                mma_bf16(sc[2 * j2 + 1], al, &th[2]);
            }
        }

        // ---- masks + online softmax ----
#pragma unroll
        for (int j = 0; j < 8; j++) {
            int c = j * 8 + (lane & 3) * 2;
            float2 pd = *(float2*)&pads[c];
            float m00 = 0.f, m01 = 0.f, m10 = 0.f, m11 = 0.f;
            if (diag || full_mask_tile) {
                float2 a = *(const float2*)(look_mask + (size_t)(q0 + rl0) * S_LEN + k0 + c);
                float2 d = *(const float2*)(look_mask + (size_t)(q0 + rl1) * S_LEN + k0 + c);
                m00 = a.x; m01 = a.y; m10 = d.x; m11 = d.y;
            }
            sc[j][0] = sc[j][0] * 0.125f + pd.x + m00;
            sc[j][1] = sc[j][1] * 0.125f + pd.y + m01;
            sc[j][2] = sc[j][2] * 0.125f + pd.x + m10;
            sc[j][3] = sc[j][3] * 0.125f + pd.y + m11;
        }
        float tm0 = -INFINITY, tm1 = -INFINITY;
#pragma unroll
        for (int j = 0; j < 8; j++) {
            tm0 = fmaxf(tm0, fmaxf(sc[j][0], sc[j][1]));
            tm1 = fmaxf(tm1, fmaxf(sc[j][2], sc[j][3]));
        }
        tm0 = fmaxf(tm0, __shfl_xor_sync(0xffffffffu, tm0, 1));
        tm0 = fmaxf(tm0, __shfl_xor_sync(0xffffffffu, tm0, 2));
        tm1 = fmaxf(tm1, __shfl_xor_sync(0xffffffffu, tm1, 1));
        tm1 = fmaxf(tm1, __shfl_xor_sync(0xffffffffu, tm1, 2));

        const float mn0 = fmaxf(mrow[0], tm0);
        const float mn1 = fmaxf(mrow[1], tm1);
        const float corr0 = __expf(mrow[0] - mn0);
        const float corr1 = __expf(mrow[1] - mn1);
        float rs0 = 0.0f, rs1 = 0.0f;
#pragma unroll
        for (int j = 0; j < 8; j++) {
            sc[j][0] = __expf(sc[j][0] - mn0);
            sc[j][1] = __expf(sc[j][1] - mn0);
            sc[j][2] = __expf(sc[j][2] - mn1);
            sc[j][3] = __expf(sc[j][3] - mn1);
            rs0 += sc[j][0] + sc[j][1];
            rs1 += sc[j][2] + sc[j][3];
        }
        rs0 += __shfl_xor_sync(0xffffffffu, rs0, 1);
        rs0 += __shfl_xor_sync(0xffffffffu, rs0, 2);
        rs1 += __shfl_xor_sync(0xffffffffu, rs1, 1);
        rs1 += __shfl_xor_sync(0xffffffffu, rs1, 2);
        lrow[0] = lrow[0] * corr0 + rs0; mrow[0] = mn0;
        lrow[1] = lrow[1] * corr1 + rs1; mrow[1] = mn1;
#pragma unroll
        for (int j = 0; j < 8; j++) {
            o[j][0] *= corr0; o[j][1] *= corr0;
            o[j][2] *= corr1; o[j][3] *= corr1;
        }

        // ---- store P hi/lo (warp-private rows) ----
#pragma unroll
        for (int j = 0; j < 8; j++) {
            int c = j * 8 + (lane & 3) * 2;
            __nv_bfloat162 h0, l0, h1, l1;
            h0.x = __float2bfloat16(sc[j][0]); l0.x = __float2bfloat16(sc[j][0] - __bfloat162float(h0.x));
            h0.y = __float2bfloat16(sc[j][1]); l0.y = __float2bfloat16(sc[j][1] - __bfloat162float(h0.y));
            h1.x = __float2bfloat16(sc[j][2]); l1.x = __float2bfloat16(sc[j][2] - __bfloat162float(h1.x));
            h1.y = __float2bfloat16(sc[j][3]); l1.y = __float2bfloat16(sc[j][3] - __bfloat162float(h1.y));
            *(__nv_bfloat162*)(smc + FL_PH + (rl0 * FL_STRIDE + c) * 2) = h0;
            *(__nv_bfloat162*)(smc + FL_PL + (rl0 * FL_STRIDE + c) * 2) = l0;
            *(__nv_bfloat162*)(smc + FL_PH + (rl1 * FL_STRIDE + c) * 2) = h1;
            *(__nv_bfloat162*)(smc + FL_PL + (rl1 * FL_STRIDE + c) * 2) = l1;
        }

        // ---- O += P @ V ----
#pragma unroll
        for (int ks = 0; ks < 4; ks++) {
            uint32_t ah[4], al[4];
            {
                int row = warp * 16 + (lane & 15);
                int col = ks * 16 + (lane >> 4) * 8;
                uint32_t off = (row * FL_STRIDE + col) * 2;
                ldsm_x4(ah, uPH + off);
                ldsm_x4(al, uPL + off);
            }
#pragma unroll
            for (int j2 = 0; j2 < 4; j2++) {
                int vr = ks * 16 + (lane & 7) + ((lane & 8) ? 8 : 0);
                int vc = j2 * 16 + ((lane & 16) ? 8 : 0);
                uint32_t off = (vr * FL_STRIDE + vc) * 2;
                uint32_t th[4], tl[4];
                ldsm_x4_t(th, uVH + off);
                ldsm_x4_t(tl, uVL + off);
                mma_bf16(o[2 * j2],     ah, &th[0]);
                mma_bf16(o[2 * j2],     ah, &tl[0]);
                mma_bf16(o[2 * j2],     al, &th[0]);
                mma_bf16(o[2 * j2 + 1], ah, &th[2]);
                mma_bf16(o[2 * j2 + 1], ah, &tl[2]);
                mma_bf16(o[2 * j2 + 1], al, &th[2]);
            }
        }
        __syncthreads();   // all warps done with this K/V buffer before reuse
    }

    // ---- epilogue: normalize, write O hi/lo ----
    const float inv0 = 1.0f / lrow[0];
    const float inv1 = 1.0f / lrow[1];
    const size_t rg0 = (size_t)(b * S_LEN + q0 + rl0);
#pragma unroll
    for (int j = 0; j < 8; j++) {
        size_t c = hoff + j * 8 + (lane & 3) * 2;
        float v00 = o[j][0] * inv0, v01 = o[j][1] * inv0;
        float v10 = o[j][2] * inv1, v11 = o[j][3] * inv1;
        ushort2 h0, l0, h1, l1;
        split1(v00, h0.x, l0.x); split1(v01, h0.y, l0.y);
        split1(v10, h1.x, l1.x); split1(v11, h1.y, l1.y);
        *(ushort2*)&g_Ohi[rg0 * DMODEL + c] = h0;
        *(ushort2*)&g_Olo[rg0 * DMODEL + c] = l0;
        *(ushort2*)&g_Ohi[(rg0 + 8) * DMODEL + c] = h1;
        *(ushort2*)&g_Olo[(rg0 + 8) * DMODEL + c] = l1;
    }
}

// ---------------------------------------------------------------------------
// Launch
// ---------------------------------------------------------------------------
extern "C" void kernel_launch(void* const* d_in, const int* in_sizes, int n_in,
                              void* d_out, int out_size) {
    const float* query = (const float*)d_in[0];
    const float* key   = (const float*)d_in[1];
    const float* value = (const float*)d_in[2];
    const float* pad   = (const float*)d_in[3];
    const float* look  = (const float*)d_in[4];
    const float* wq    = (const float*)d_in[5];
    const float* wk    = (const float*)d_in[6];
    const float* wv    = (const float*)d_in[7];
    const float* wo    = (const float*)d_in[8];
    const float* bq    = (const float*)d_in[9];
    const float* bk    = (const float*)d_in[10];
    const float* bv    = (const float*)d_in[11];
    const float* bo    = (const float*)d_in[12];
    float* out = (float*)d_out;

    cudaFuncSetAttribute(flash_mma,   cudaFuncAttributeMaxDynamicSharedMemorySize, FL_SMEM);
    cudaFuncSetAttribute(gemm_qkv_tc, cudaFuncAttributeMaxDynamicSharedMemorySize, GEMM_SMEM);
    cudaFuncSetAttribute(gemm_out_tc, cudaFuncAttributeMaxDynamicSharedMemorySize, GEMM_SMEM);

    const int n4 = MROWS * DMODEL / 4;

    // 1) split activations (q,k,v in one launch)
    dim3 gs(n4 / 256, 3);
    split3_kernel<<<gs, 256>>>(query, key, value, n4);

    // 2) transpose + split weights
    dim3 gw(DMODEL / 32, DMODEL / 32, 4);
    wsplit_kernel<<<gw, 256>>>(wq, wk, wv, wo);

    // 3) QKV projections (HMMA bf16x3, bf16 hi/lo outputs)
    dim3 gq(DMODEL / 128, MROWS / 128, 3);
    gemm_qkv_tc<<<gq, 256, GEMM_SMEM>>>(bq, bk, bv);

    // 4) causal flash attention (128-row q-tiles, pre-split inputs)
    dim3 ga(S_LEN / 128, NHEADS, BATCH);
    flash_mma<<<ga, 256, FL_SMEM>>>(pad, look);

    // 5) output projection -> d_out
    dim3 go(DMODEL / 128, MROWS / 128, 1);
    gemm_out_tc<<<go, 256, GEMM_SMEM>>>(bo, out);
}

// round 5
// speedup vs baseline: 1.0571x; 1.0571x over previous
#include <cuda_runtime.h>
#include <cuda_bf16.h>
#include <math.h>
#include <stdint.h>

#define S_LEN   2048
#define DMODEL  1024
#define NHEADS  16
#define DK      64
#define BATCH   2
#define MROWS   (BATCH * S_LEN)   // 4096

typedef unsigned short ushort_t;

// ---------------------------------------------------------------------------
// Device scratch
// ---------------------------------------------------------------------------
__device__ __align__(16) ushort_t g_Xhi[(size_t)MROWS * DMODEL];
__device__ __align__(16) ushort_t g_Xlo[(size_t)MROWS * DMODEL];
__device__ __align__(16) ushort_t g_Yhi[(size_t)MROWS * DMODEL];
__device__ __align__(16) ushort_t g_Ylo[(size_t)MROWS * DMODEL];
__device__ __align__(16) ushort_t g_Zhi[(size_t)MROWS * DMODEL];
__device__ __align__(16) ushort_t g_Zlo[(size_t)MROWS * DMODEL];
__device__ __align__(16) ushort_t g_Qhi[(size_t)MROWS * DMODEL];
__device__ __align__(16) ushort_t g_Qlo[(size_t)MROWS * DMODEL];
__device__ __align__(16) ushort_t g_Khi[(size_t)MROWS * DMODEL];
__device__ __align__(16) ushort_t g_Klo[(size_t)MROWS * DMODEL];
__device__ __align__(16) ushort_t g_Vhi[(size_t)MROWS * DMODEL];
__device__ __align__(16) ushort_t g_Vlo[(size_t)MROWS * DMODEL];
__device__ __align__(16) ushort_t g_Ohi[(size_t)MROWS * DMODEL];
__device__ __align__(16) ushort_t g_Olo[(size_t)MROWS * DMODEL];
__device__ __align__(16) ushort_t g_WqThi[(size_t)DMODEL * DMODEL];
__device__ __align__(16) ushort_t g_WqTlo[(size_t)DMODEL * DMODEL];
__device__ __align__(16) ushort_t g_WkThi[(size_t)DMODEL * DMODEL];
__device__ __align__(16) ushort_t g_WkTlo[(size_t)DMODEL * DMODEL];
__device__ __align__(16) ushort_t g_WvThi[(size_t)DMODEL * DMODEL];
__device__ __align__(16) ushort_t g_WvTlo[(size_t)DMODEL * DMODEL];
__device__ __align__(16) ushort_t g_WoThi[(size_t)DMODEL * DMODEL];
__device__ __align__(16) ushort_t g_WoTlo[(size_t)DMODEL * DMODEL];

// ---------------------------------------------------------------------------
// Low-level helpers
// ---------------------------------------------------------------------------
__device__ __forceinline__ uint32_t smem_u32(const void* p) {
    uint32_t a;
    asm("{ .reg .u64 t; cvta.to.shared.u64 t, %1; cvt.u32.u64 %0, t; }" : "=r"(a) : "l"(p));
    return a;
}
__device__ __forceinline__ void mma_bf16(float* c, const uint32_t* a, const uint32_t* b) {
    asm volatile(
        "mma.sync.aligned.m16n8k16.row.col.f32.bf16.bf16.f32 "
        "{%0,%1,%2,%3}, {%4,%5,%6,%7}, {%8,%9}, {%0,%1,%2,%3};"
        : "+f"(c[0]), "+f"(c[1]), "+f"(c[2]), "+f"(c[3])
        : "r"(a[0]), "r"(a[1]), "r"(a[2]), "r"(a[3]), "r"(b[0]), "r"(b[1]));
}
__device__ __forceinline__ void ldsm_x4(uint32_t* r, uint32_t addr) {
    asm volatile("ldmatrix.sync.aligned.m8n8.x4.shared.b16 {%0,%1,%2,%3}, [%4];"
        : "=r"(r[0]), "=r"(r[1]), "=r"(r[2]), "=r"(r[3]) : "r"(addr));
}
__device__ __forceinline__ void ldsm_x4_t(uint32_t* r, uint32_t addr) {
    asm volatile("ldmatrix.sync.aligned.m8n8.x4.trans.shared.b16 {%0,%1,%2,%3}, [%4];"
        : "=r"(r[0]), "=r"(r[1]), "=r"(r[2]), "=r"(r[3]) : "r"(addr));
}
__device__ __forceinline__ void cp16(uint32_t dst, const void* src) {
    asm volatile("cp.async.cg.shared.global [%0], [%1], 16;" :: "r"(dst), "l"(src));
}
__device__ __forceinline__ void cp_commit() {
    asm volatile("cp.async.commit_group;" ::: "memory");
}
template <int N> __device__ __forceinline__ void cp_wait() {
    asm volatile("cp.async.wait_group %0;" :: "n"(N) : "memory");
}
__device__ __forceinline__ void split1(float x, ushort_t& h, ushort_t& l) {
    __nv_bfloat16 hb = __float2bfloat16(x);
    float rem = x - __bfloat162float(hb);
    __nv_bfloat16 lb = __float2bfloat16(rem);
    h = __bfloat16_as_ushort(hb);
    l = __bfloat16_as_ushort(lb);
}
// pack two floats into bf16x2 hi and lo-residual words (low 16 bits = first elem)
__device__ __forceinline__ void pack2_hl(float x, float y, uint32_t& h, uint32_t& l) {
    ushort_t hx, lx, hy, ly;
    split1(x, hx, lx);
    split1(y, hy, ly);
    h = (uint32_t)hx | ((uint32_t)hy << 16);
    l = (uint32_t)lx | ((uint32_t)ly << 16);
}

// ---------------------------------------------------------------------------
// Prep kernels
// ---------------------------------------------------------------------------
__global__ void __launch_bounds__(256) split3_kernel(const float* __restrict__ x0,
                                                     const float* __restrict__ x1,
                                                     const float* __restrict__ x2,
                                                     int n4) {
    const float* x;
    ushort_t *hi, *lo;
    switch (blockIdx.y) {
        case 0:  x = x0; hi = g_Xhi; lo = g_Xlo; break;
        case 1:  x = x1; hi = g_Yhi; lo = g_Ylo; break;
        default: x = x2; hi = g_Zhi; lo = g_Zlo; break;
    }
    int i = blockIdx.x * 256 + threadIdx.x;
    if (i >= n4) return;
    float4 v = ((const float4*)x)[i];
    ushort4 h, l;
    split1(v.x, h.x, l.x);
    split1(v.y, h.y, l.y);
    split1(v.z, h.z, l.z);
    split1(v.w, h.w, l.w);
    ((ushort4*)hi)[i] = h;
    ((ushort4*)lo)[i] = l;
}

__global__ void __launch_bounds__(256) wsplit_kernel(const float* __restrict__ w0,
                                                     const float* __restrict__ w1,
                                                     const float* __restrict__ w2,
                                                     const float* __restrict__ w3) {
    __shared__ float t[32][33];
    const float* W;
    ushort_t *TH, *TL;
    switch (blockIdx.z) {
        case 0: W = w0; TH = g_WqThi; TL = g_WqTlo; break;
        case 1: W = w1; TH = g_WkThi; TL = g_WkTlo; break;
        case 2: W = w2; TH = g_WvThi; TL = g_WvTlo; break;
        default: W = w3; TH = g_WoThi; TL = g_WoTlo; break;
    }
    int tx = threadIdx.x & 31, ty = threadIdx.x >> 5;
    int n0 = blockIdx.x * 32, k0 = blockIdx.y * 32;
#pragma unroll
    for (int j = 0; j < 4; j++)
        t[ty + 8 * j][tx] = W[(size_t)(k0 + ty + 8 * j) * DMODEL + n0 + tx];
    __syncthreads();
#pragma unroll
    for (int j = 0; j < 4; j++) {
        float v = t[tx][ty + 8 * j];
        ushort_t h, l;
        split1(v, h, l);
        size_t o = (size_t)(n0 + ty + 8 * j) * DMODEL + k0 + tx;
        TH[o] = h;
        TL[o] = l;
    }
}

// ---------------------------------------------------------------------------
// HMMA GEMM (bf16x3), 128x128x32 tiles, cp.async double buffer.
// ---------------------------------------------------------------------------
#define GT_STRIDE 40
#define GT_MAT    (128 * GT_STRIDE * 2)
#define GT_BUF    (4 * GT_MAT)
#define GEMM_SMEM (2 * GT_BUF)

template <bool SPLIT_OUT>
__device__ __forceinline__ void gemm_mma_body(const ushort_t* __restrict__ ahi,
                                              const ushort_t* __restrict__ alo,
                                              const ushort_t* __restrict__ bhi,
                                              const ushort_t* __restrict__ blo,
                                              const float* __restrict__ bias,
                                              float* __restrict__ Cf,
                                              ushort_t* __restrict__ Chi,
                                              ushort_t* __restrict__ Clo) {
    extern __shared__ char smem[];
    const uint32_t sb = smem_u32(smem);
    const int tid = threadIdx.x;
    const int lane = tid & 31;
    const int wid = tid >> 5;
    const int wm = wid >> 1;
    const int wn = wid & 1;
    const int m0 = blockIdx.y * 128;
    const int n0 = blockIdx.x * 128;

    const ushort_t* srcs[4] = { ahi + (size_t)m0 * DMODEL, alo + (size_t)m0 * DMODEL,
                                bhi + (size_t)n0 * DMODEL, blo + (size_t)n0 * DMODEL };

    auto load_chunk = [&](int c, int buf) {
        uint32_t dbase = sb + buf * GT_BUF;
#pragma unroll
        for (int mt = 0; mt < 4; mt++) {
#pragma unroll
            for (int i = 0; i < 2; i++) {
                int idx = tid + i * 256;
                int row = idx >> 2, seg = idx & 3;
                const ushort_t* src = srcs[mt] + (size_t)row * DMODEL + c * 32 + seg * 8;
                cp16(dbase + mt * GT_MAT + (row * GT_STRIDE + seg * 8) * 2, src);
            }
        }
    };

    float acc[2][8][4];
#pragma unroll
    for (int mi = 0; mi < 2; mi++)
#pragma unroll
        for (int j = 0; j < 8; j++)
#pragma unroll
            for (int q = 0; q < 4; q++) acc[mi][j][q] = 0.0f;

    load_chunk(0, 0);
    cp_commit();

    for (int c = 0; c < 32; c++) {
        if (c + 1 < 32) { load_chunk(c + 1, (c + 1) & 1); cp_commit(); }
        if (c + 1 < 32) cp_wait<1>(); else cp_wait<0>();
        __syncthreads();

        const uint32_t base = sb + (c & 1) * GT_BUF;
        const uint32_t A_h = base, A_l = base + GT_MAT;
        const uint32_t B_h = base + 2 * GT_MAT, B_l = base + 3 * GT_MAT;
#pragma unroll
        for (int ks = 0; ks < 2; ks++) {
            uint32_t ah[2][4], al[2][4];
#pragma unroll
            for (int mi = 0; mi < 2; mi++) {
                int row = wm * 32 + mi * 16 + (lane & 15);
                int col = ks * 16 + (lane >> 4) * 8;
                uint32_t off = (row * GT_STRIDE + col) * 2;
                ldsm_x4(ah[mi], A_h + off);
                ldsm_x4(al[mi], A_l + off);
            }
            uint32_t bh[8][2], bl[8][2];
#pragma unroll
            for (int j2 = 0; j2 < 4; j2++) {
                int nr = wn * 64 + j2 * 16 + (lane & 7) + ((lane & 16) ? 8 : 0);
                int kc = ks * 16 + ((lane & 8) ? 8 : 0);
                uint32_t off = (nr * GT_STRIDE + kc) * 2;
                uint32_t t[4];
                ldsm_x4(t, B_h + off);
                bh[2 * j2][0] = t[0]; bh[2 * j2][1] = t[1];
                bh[2 * j2 + 1][0] = t[2]; bh[2 * j2 + 1][1] = t[3];
                ldsm_x4(t, B_l + off);
                bl[2 * j2][0] = t[0]; bl[2 * j2][1] = t[1];
                bl[2 * j2 + 1][0] = t[2]; bl[2 * j2 + 1][1] = t[3];
            }
#pragma unroll
            for (int mi = 0; mi < 2; mi++)
#pragma unroll
                for (int j = 0; j < 8; j++) {
                    mma_bf16(acc[mi][j], ah[mi], bh[j]);
                    mma_bf16(acc[mi][j], ah[mi], bl[j]);
                    mma_bf16(acc[mi][j], al[mi], bh[j]);
                }
        }
        __syncthreads();
    }

#pragma unroll
    for (int mi = 0; mi < 2; mi++) {
#pragma unroll
        for (int j = 0; j < 8; j++) {
            int row = m0 + wm * 32 + mi * 16 + (lane >> 2);
            int col = n0 + wn * 64 + j * 8 + (lane & 3) * 2;
            float2 bb = *(const float2*)&bias[col];
            float v00 = acc[mi][j][0] + bb.x, v01 = acc[mi][j][1] + bb.y;
            float v10 = acc[mi][j][2] + bb.x, v11 = acc[mi][j][3] + bb.y;
            if (SPLIT_OUT) {
                ushort2 h0, l0, h1, l1;
                split1(v00, h0.x, l0.x); split1(v01, h0.y, l0.y);
                split1(v10, h1.x, l1.x); split1(v11, h1.y, l1.y);
                *(ushort2*)&Chi[(size_t)row * DMODEL + col] = h0;
                *(ushort2*)&Clo[(size_t)row * DMODEL + col] = l0;
                *(ushort2*)&Chi[(size_t)(row + 8) * DMODEL + col] = h1;
                *(ushort2*)&Clo[(size_t)(row + 8) * DMODEL + col] = l1;
            } else {
                float2 w0 = { v00, v01 }, w1 = { v10, v11 };
                *(float2*)&Cf[(size_t)row * DMODEL + col] = w0;
                *(float2*)&Cf[(size_t)(row + 8) * DMODEL + col] = w1;
            }
        }
    }
}

__global__ void __launch_bounds__(256) gemm_qkv_tc(const float* __restrict__ bq,
                                                   const float* __restrict__ bk,
                                                   const float* __restrict__ bv) {
    if (blockIdx.z == 0)
        gemm_mma_body<true>(g_Xhi, g_Xlo, g_WqThi, g_WqTlo, bq, nullptr, g_Qhi, g_Qlo);
    else if (blockIdx.z == 1)
        gemm_mma_body<true>(g_Yhi, g_Ylo, g_WkThi, g_WkTlo, bk, nullptr, g_Khi, g_Klo);
    else
        gemm_mma_body<true>(g_Zhi, g_Zlo, g_WvThi, g_WvTlo, bv, nullptr, g_Vhi, g_Vlo);
}

__global__ void __launch_bounds__(256) gemm_out_tc(const float* __restrict__ bo,
                                                   float* __restrict__ C) {
    gemm_mma_body<false>(g_Ohi, g_Olo, g_WoThi, g_WoTlo, bo, C, nullptr, nullptr);
}

// ---------------------------------------------------------------------------
// HMMA flash attention: 128 q-rows, 256 threads / 8 warps, register-resident P.
// smem: Q hi/lo + double-buffered K/V hi/lo + pads = 110.8 KB -> 2 CTA/SM.
// ---------------------------------------------------------------------------
#define FL_STRIDE 72
#define FL_QT  (128 * FL_STRIDE * 2)     // 18432 B
#define FL_KVT (64 * FL_STRIDE * 2)      // 9216 B
#define FL_KVBUF (4 * FL_KVT)            // KH,KL,VH,VL
#define FL_QH  0
#define FL_QL  (FL_QH + FL_QT)
#define FL_KV  (FL_QL + FL_QT)
#define FL_PAD (FL_KV + 2 * FL_KVBUF)
#define FL_SMEM (FL_PAD + 256)           // 110848 B

__global__ void __launch_bounds__(256, 2) flash_mma(const float* __restrict__ pad_mask,
                                                    const float* __restrict__ look_mask) {
    extern __shared__ char smc[];
    const uint32_t sb = smem_u32(smc);
    const uint32_t uQH = sb + FL_QH, uQL = sb + FL_QL;
    float* pads = (float*)(smc + FL_PAD);

    const int tid = threadIdx.x;
    const int lane = tid & 31;
    const int warp = tid >> 5;
    const int qt = (S_LEN / 128 - 1) - blockIdx.x;   // heavy tiles first
    const int h = blockIdx.y, b = blockIdx.z;
    const int q0 = qt * 128;

    const size_t hoff = (size_t)h * DK;

    {
        const ushort_t* QH = g_Qhi + (size_t)(b * S_LEN + q0) * DMODEL + hoff;
        const ushort_t* QL = g_Qlo + (size_t)(b * S_LEN + q0) * DMODEL + hoff;
#pragma unroll
        for (int i = 0; i < 8; i++) {
            int idx = tid + i * 256;
            int mat = idx >> 10, rem = idx & 1023;
            int row = rem >> 3, seg = rem & 7;
            const ushort_t* src = (mat ? QL : QH) + (size_t)row * DMODEL + seg * 8;
            cp16((mat ? uQL : uQH) + (row * FL_STRIDE + seg * 8) * 2, src);
        }
    }

    auto load_kv = [&](int kt, int buf) {
        const int k0 = kt * 64;
        const size_t base = (size_t)(b * S_LEN + k0) * DMODEL + hoff;
        const ushort_t* srcs[4] = { g_Khi + base, g_Klo + base, g_Vhi + base, g_Vlo + base };
        const uint32_t dbase = sb + FL_KV + buf * FL_KVBUF;
#pragma unroll
        for (int i = 0; i < 8; i++) {
            int idx = tid + i * 256;
            int sel = idx >> 9, rem = idx & 511;
            int row = rem >> 3, seg = rem & 7;
            cp16(dbase + sel * FL_KVT + (row * FL_STRIDE + seg * 8) * 2,
                 srcs[sel] + (size_t)row * DMODEL + seg * 8);
        }
    };

    const int nkt = 2 * qt + 2;
    load_kv(0, 0);
    cp_commit();

    float o[8][4];
    float mrow[2] = { -INFINITY, -INFINITY };
    float lrow[2] = { 0.0f, 0.0f };
#pragma unroll
    for (int j = 0; j < 8; j++)
#pragma unroll
        for (int q = 0; q < 4; q++) o[j][q] = 0.0f;

    const int rl0 = warp * 16 + (lane >> 2);
    const int rl1 = rl0 + 8;
    const int r_lo = q0 + warp * 16;        // warp's lowest q row
    const int r_hi = r_lo + 15;             // warp's highest q row

    for (int kt = 0; kt < nkt; kt++) {
        const int buf = kt & 1;
        const int k0 = kt * 64;
        if (kt + 1 < nkt) { load_kv(kt + 1, buf ^ 1); cp_commit(); }
        if (tid < 64) pads[tid] = pad_mask[b * S_LEN + k0 + tid];
        if (kt + 1 < nkt) cp_wait<1>(); else cp_wait<0>();
        __syncthreads();

        // fully-masked tile for this warp: contributes exactly 0 after softmax
        const bool active = (k0 <= r_hi);

        if (active) {
            const uint32_t kvb = sb + FL_KV + buf * FL_KVBUF;
            const uint32_t uKH = kvb, uKL = kvb + FL_KVT;
            const uint32_t uVH = kvb + 2 * FL_KVT, uVL = kvb + 3 * FL_KVT;
            const bool diag = (k0 + 63 >= r_lo);   // mask needed on partial overlap

            // ---- S = Q @ K^T ----
            float sc[8][4];
#pragma unroll
            for (int j = 0; j < 8; j++)
#pragma unroll
                for (int q = 0; q < 4; q++) sc[j][q] = 0.0f;

#pragma unroll
            for (int ks = 0; ks < 4; ks++) {
                uint32_t ah[4], al[4];
                {
                    int row = warp * 16 + (lane & 15);
                    int col = ks * 16 + (lane >> 4) * 8;
                    uint32_t off = (row * FL_STRIDE + col) * 2;
                    ldsm_x4(ah, uQH + off);
                    ldsm_x4(al, uQL + off);
                }
#pragma unroll
                for (int j2 = 0; j2 < 4; j2++) {
                    int nr = j2 * 16 + (lane & 7) + ((lane & 16) ? 8 : 0);
                    int kc = ks * 16 + ((lane & 8) ? 8 : 0);
                    uint32_t off = (nr * FL_STRIDE + kc) * 2;
                    uint32_t th[4], tl[4];
                    ldsm_x4(th, uKH + off);
                    ldsm_x4(tl, uKL + off);
                    mma_bf16(sc[2 * j2],     ah, &th[0]);
                    mma_bf16(sc[2 * j2],     ah, &tl[0]);
                    mma_bf16(sc[2 * j2],     al, &th[0]);
                    mma_bf16(sc[2 * j2 + 1], ah, &th[2]);
                    mma_bf16(sc[2 * j2 + 1], ah, &tl[2]);
                    mma_bf16(sc[2 * j2 + 1], al, &th[2]);
                }
            }

            // ---- masks + online softmax ----
#pragma unroll
            for (int j = 0; j < 8; j++) {
                int c = j * 8 + (lane & 3) * 2;
                float2 pd = *(float2*)&pads[c];
                float m00 = 0.f, m01 = 0.f, m10 = 0.f, m11 = 0.f;
                if (diag) {
                    float2 a = *(const float2*)(look_mask + (size_t)(q0 + rl0) * S_LEN + k0 + c);
                    float2 d = *(const float2*)(look_mask + (size_t)(q0 + rl1) * S_LEN + k0 + c);
                    m00 = a.x; m01 = a.y; m10 = d.x; m11 = d.y;
                }
                sc[j][0] = sc[j][0] * 0.125f + pd.x + m00;
                sc[j][1] = sc[j][1] * 0.125f + pd.y + m01;
                sc[j][2] = sc[j][2] * 0.125f + pd.x + m10;
                sc[j][3] = sc[j][3] * 0.125f + pd.y + m11;
            }
            float tm0 = -INFINITY, tm1 = -INFINITY;
#pragma unroll
            for (int j = 0; j < 8; j++) {
                tm0 = fmaxf(tm0, fmaxf(sc[j][0], sc[j][1]));
                tm1 = fmaxf(tm1, fmaxf(sc[j][2], sc[j][3]));
            }
            tm0 = fmaxf(tm0, __shfl_xor_sync(0xffffffffu, tm0, 1));
            tm0 = fmaxf(tm0, __shfl_xor_sync(0xffffffffu, tm0, 2));
            tm1 = fmaxf(tm1, __shfl_xor_sync(0xffffffffu, tm1, 1));
            tm1 = fmaxf(tm1, __shfl_xor_sync(0xffffffffu, tm1, 2));

            const float mn0 = fmaxf(mrow[0], tm0);
            const float mn1 = fmaxf(mrow[1], tm1);
            const float corr0 = __expf(mrow[0] - mn0);
            const float corr1 = __expf(mrow[1] - mn1);
            float rs0 = 0.0f, rs1 = 0.0f;
#pragma unroll
            for (int j = 0; j < 8; j++) {
                sc[j][0] = __expf(sc[j][0] - mn0);
                sc[j][1] = __expf(sc[j][1] - mn0);
                sc[j][2] = __expf(sc[j][2] - mn1);
                sc[j][3] = __expf(sc[j][3] - mn1);
                rs0 += sc[j][0] + sc[j][1];
                rs1 += sc[j][2] + sc[j][3];
            }
            rs0 += __shfl_xor_sync(0xffffffffu, rs0, 1);
            rs0 += __shfl_xor_sync(0xffffffffu, rs0, 2);
            rs1 += __shfl_xor_sync(0xffffffffu, rs1, 1);
            rs1 += __shfl_xor_sync(0xffffffffu, rs1, 2);
            lrow[0] = lrow[0] * corr0 + rs0; mrow[0] = mn0;
            lrow[1] = lrow[1] * corr1 + rs1; mrow[1] = mn1;
#pragma unroll
            for (int j = 0; j < 8; j++) {
                o[j][0] *= corr0; o[j][1] *= corr0;
                o[j][2] *= corr1; o[j][3] *= corr1;
            }

            // ---- O += P @ V : P stays in registers (C-frag == A-frag layout) ----
#pragma unroll
            for (int ks = 0; ks < 4; ks++) {
                uint32_t ah[4], al[4];
                pack2_hl(sc[2 * ks][0],     sc[2 * ks][1],     ah[0], al[0]);
                pack2_hl(sc[2 * ks][2],     sc[2 * ks][3],     ah[1], al[1]);
                pack2_hl(sc[2 * ks + 1][0], sc[2 * ks + 1][1], ah[2], al[2]);
                pack2_hl(sc[2 * ks + 1][2], sc[2 * ks + 1][3], ah[3], al[3]);
#pragma unroll
                for (int j2 = 0; j2 < 4; j2++) {
                    int vr = ks * 16 + (lane & 7) + ((lane & 8) ? 8 : 0);
                    int vc = j2 * 16 + ((lane & 16) ? 8 : 0);
                    uint32_t off = (vr * FL_STRIDE + vc) * 2;
                    uint32_t th[4], tl[4];
                    ldsm_x4_t(th, uVH + off);
                    ldsm_x4_t(tl, uVL + off);
                    mma_bf16(o[2 * j2],     ah, &th[0]);
                    mma_bf16(o[2 * j2],     ah, &tl[0]);
                    mma_bf16(o[2 * j2],     al, &th[0]);
                    mma_bf16(o[2 * j2 + 1], ah, &th[2]);
                    mma_bf16(o[2 * j2 + 1], ah, &tl[2]);
                    mma_bf16(o[2 * j2 + 1], al, &th[2]);
                }
            }
        }
        __syncthreads();   // all warps done with this K/V buffer before overwrite
    }

    // ---- epilogue ----
    const float inv0 = 1.0f / lrow[0];
    const float inv1 = 1.0f / lrow[1];
    const size_t rg0 = (size_t)(b * S_LEN + q0 + rl0);
#pragma unroll
    for (int j = 0; j < 8; j++) {
        size_t c = hoff + j * 8 + (lane & 3) * 2;
        float v00 = o[j][0] * inv0, v01 = o[j][1] * inv0;
        float v10 = o[j][2] * inv1, v11 = o[j][3] * inv1;
        ushort2 h0, l0, h1, l1;
        split1(v00, h0.x, l0.x); split1(v01, h0.y, l0.y);
        split1(v10, h1.x, l1.x); split1(v11, h1.y, l1.y);
        *(ushort2*)&g_Ohi[rg0 * DMODEL + c] = h0;
        *(ushort2*)&g_Olo[rg0 * DMODEL + c] = l0;
        *(ushort2*)&g_Ohi[(rg0 + 8) * DMODEL + c] = h1;
        *(ushort2*)&g_Olo[(rg0 + 8) * DMODEL + c] = l1;
    }
}

// ---------------------------------------------------------------------------
// Launch
// ---------------------------------------------------------------------------
extern "C" void kernel_launch(void* const* d_in, const int* in_sizes, int n_in,
                              void* d_out, int out_size) {
    const float* query = (const float*)d_in[0];
    const float* key   = (const float*)d_in[1];
    const float* value = (const float*)d_in[2];
    const float* pad   = (const float*)d_in[3];
    const float* look  = (const float*)d_in[4];
    const float* wq    = (const float*)d_in[5];
    const float* wk    = (const float*)d_in[6];
    const float* wv    = (const float*)d_in[7];
    const float* wo    = (const float*)d_in[8];
    const float* bq    = (const float*)d_in[9];
    const float* bk    = (const float*)d_in[10];
    const float* bv    = (const float*)d_in[11];
    const float* bo    = (const float*)d_in[12];
    float* out = (float*)d_out;

    cudaFuncSetAttribute(flash_mma,   cudaFuncAttributeMaxDynamicSharedMemorySize, FL_SMEM);
    cudaFuncSetAttribute(gemm_qkv_tc, cudaFuncAttributeMaxDynamicSharedMemorySize, GEMM_SMEM);
    cudaFuncSetAttribute(gemm_out_tc, cudaFuncAttributeMaxDynamicSharedMemorySize, GEMM_SMEM);

    const int n4 = MROWS * DMODEL / 4;

    dim3 gs(n4 / 256, 3);
    split3_kernel<<<gs, 256>>>(query, key, value, n4);

    dim3 gw(DMODEL / 32, DMODEL / 32, 4);
    wsplit_kernel<<<gw, 256>>>(wq, wk, wv, wo);

    dim3 gq(DMODEL / 128, MROWS / 128, 3);
    gemm_qkv_tc<<<gq, 256, GEMM_SMEM>>>(bq, bk, bv);

    dim3 ga(S_LEN / 128, NHEADS, BATCH);
    flash_mma<<<ga, 256, FL_SMEM>>>(pad, look);

    dim3 go(DMODEL / 128, MROWS / 128, 1);
    gemm_out_tc<<<go, 256, GEMM_SMEM>>>(bo, out);
}